// round 15
// baseline (speedup 1.0000x reference)
#include <cuda_runtime.h>

#define H 28
#define W 28
#define NSQ (H * W)          // 784 pixels
#define NE_H (H * (W - 1))   // 756
#define NE_V ((H - 1) * W)   // 756
#define NE_B (2 * H + 2 * W) // 112
#define NE (NE_H + NE_V + NE_B) // 1624
#define NT 1024
#define KMAX 1024
#define HSZ 1024
#define PMAX 512             // max dense nodes (peaks + outer); true max 393
#define CARD 50
#define EMPTY64 0xFFFFFFFFFFFFFFFFull
#define FULLM 0xffffffffu

__device__ __forceinline__ unsigned monof(float x) {
    unsigned u = __float_as_uint(x);
    return (u & 0x80000000u) ? ~u : (u | 0x80000000u);
}
__device__ __forceinline__ float invmonof(unsigned m) {
    return __uint_as_float((m & 0x80000000u) ? (m ^ 0x80000000u) : ~m);
}

__global__ __launch_bounds__(NT, 1)
void cubical_kernel(const float* __restrict__ I, const float* __restrict__ p,
                    float* __restrict__ out) {
    __shared__ float Ip[NSQ];
    __shared__ short g[NSQ];                    // ascent ptr -> peak -> dense id
    __shared__ short lbl[NSQ];                  // peak pixel -> dense id
    __shared__ unsigned long long key[KMAX];    // deduped edges / sort buffer
    __shared__ unsigned long long scratch[HSZ]; // hash -> mst list -> pw/pd
    __shared__ int   parent[PMAX];              // Boruvka UF
    __shared__ float cmaxv[PMAX];
    __shared__ unsigned long long best[PMAX];
    __shared__ int2  node2[PMAX];               // scan UF: .x parent, .y cmax bits
    __shared__ int cnt_peaks, ecnt, nmst, npairs, smem_M;

    const int t = threadIdx.x;
    const int lane = t & 31;
    const int warp = t >> 5;
    const unsigned ltm = (1u << lane) - 1u;
    const float p0 = p[0], p1 = p[1];

    // ---- Phase 1: Ip = I.p, init ----
    if (t < NSQ) Ip[t] = fmaf(I[2 * t], p0, I[2 * t + 1] * p1);
    if (t == 0) { cnt_peaks = 0; ecnt = 0; nmst = 0; npairs = 0; }
    if (t < HSZ) scratch[t] = EMPTY64;
    if (t < PMAX) { parent[t] = t; best[t] = 0ull; }
    __syncthreads();

    // ---- Phase 2: steepest-ascent pointer ----
    if (t < NSQ) {
        const int row = t / W, col = t - row * W;
        float bf = Ip[t]; int bid = t;
        if (col > 0)     { float f = Ip[t - 1]; if (f > bf) { bf = f; bid = t - 1; } }
        if (col < W - 1) { float f = Ip[t + 1]; if (f > bf) { bf = f; bid = t + 1; } }
        if (row > 0)     { float f = Ip[t - W]; if (f > bf) { bf = f; bid = t - W; } }
        if (row < H - 1) { float f = Ip[t + W]; if (f > bf) { bf = f; bid = t + W; } }
        g[t] = (short)bid;
    }
    __syncthreads();

    // ---- Phase 3: register chase to peak (read-only ascent forest: acyclic) ----
    short gfin = 0;
    if (t < NSQ) {
        int x = t, gx = g[x];
        while (gx != x) { x = gx; gx = g[x]; }
        gfin = (short)x;
    }
    __syncthreads();
    if (t < NSQ) g[t] = gfin;
    __syncthreads();

    // ---- Phase 3.5: dense relabel of peaks (warp-aggregated counter) ----
    {
        bool isPeak = (t < NSQ) && (g[t] == (short)t);
        unsigned m = __ballot_sync(FULLM, isPeak);
        int base = 0;
        if (m) {
            int ldr = __ffs(m) - 1;
            if (lane == ldr) base = atomicAdd(&cnt_peaks, __popc(m));
            base = __shfl_sync(FULLM, base, ldr);
        }
        if (isPeak) {
            int id = base + __popc(m & ltm);
            lbl[t] = (short)id;
            cmaxv[id] = Ip[t];
        }
    }
    __syncthreads();
    const int P = cnt_peaks;      // outer id = P
    const int NND = P + 1;
    if (t == 0) cmaxv[P] = 3.0e38f;
    short gdense = 0;
    if (t < NSQ) gdense = lbl[g[t]];
    __syncthreads();
    if (t < NSQ) g[t] = gdense;
    __syncthreads();

    // ---- Phase 4: hash dedup (max weight per peak pair) ----
    for (int i = t; i < NE; i += NT) {
        int pu, pv; float w;
        if (i < NE_H) {
            int r = i / (W - 1), c = i % (W - 1);
            int u = r * W + c, v = u + 1;
            w = fminf(Ip[u], Ip[v]);
            pu = g[u]; pv = g[v];
        } else if (i < NE_H + NE_V) {
            int j = i - NE_H;
            int u = j, v = j + W;
            w = fminf(Ip[u], Ip[v]);
            pu = g[u]; pv = g[v];
        } else {
            int j = i - NE_H - NE_V;
            int sq;
            if (j < W)              sq = j;
            else if (j < 2 * W)     sq = (H - 1) * W + (j - W);
            else if (j < 2 * W + H) sq = (j - 2 * W) * W;
            else                    sq = (j - 2 * W - H) * W + (W - 1);
            w = Ip[sq];
            pu = g[sq]; pv = P;
        }
        if (pu != pv) {
            int pmin = pu < pv ? pu : pv;
            int pmax = pu < pv ? pv : pu;
            unsigned pair = ((unsigned)pmin << 10) | (unsigned)pmax;
            unsigned long long desired = ((unsigned long long)monof(w) << 20) | pair;
            unsigned s = (pair * 2654435761u) & (HSZ - 1);
            for (;;) {
                unsigned long long cur = scratch[s];
                if (cur == EMPTY64) {
                    unsigned long long old = atomicCAS(&scratch[s], EMPTY64, desired);
                    if (old == EMPTY64) break;
                    cur = old;
                }
                if ((unsigned)(cur & 0xFFFFFu) == pair) {
                    atomicMax(&scratch[s], desired);
                    break;
                }
                s = (s + 1) & (HSZ - 1);
            }
        }
    }
    __syncthreads();

    // ---- Phase 4.5: compact hash -> key[] (aggregated) + round-0 deposit ----
    {
        unsigned long long e = scratch[t];    // t < HSZ == NT
        bool has = (e != EMPTY64);
        unsigned m = __ballot_sync(FULLM, has);
        int base = 0;
        if (m) {
            int ldr = __ffs(m) - 1;
            if (lane == ldr) base = atomicAdd(&ecnt, __popc(m));
            base = __shfl_sync(FULLM, base, ldr);
        }
        if (has) {
            key[base + __popc(m & ltm)] = e;
            unsigned pr = (unsigned)(e & 0xFFFFFull);
            atomicMax(&best[pr >> 10], e);
            atomicMax(&best[pr & 1023u], e);
        }
    }
    __syncthreads();
    const int EC = ecnt;

    // ---- Phase 5: Boruvka max-spanning-tree; exact exit at nmst == P ----
    for (int round = 0; round < 16; round++) {
        // hook + commit (aggregated)
        {
            bool commit = false;
            unsigned long long e = 0ull;
            int r = 0;
            if (t < NND) {
                e = best[t];
                if (e != 0ull && parent[t] == t) {
                    int pa = (int)((e >> 10) & 1023ull);
                    int pb = (int)(e & 1023ull);
                    r = (pa == t) ? pb : pa;
                    unsigned long long er = best[r];
                    int ra = (int)((er >> 10) & 1023ull);
                    int rb = (int)(er & 1023ull);
                    int rother = (ra == r) ? rb : ra;
                    bool mutual = (rother == t);
                    commit = !(mutual && t < r);
                }
            }
            unsigned m = __ballot_sync(FULLM, commit);
            int base = 0;
            if (m) {
                int ldr = __ffs(m) - 1;
                if (lane == ldr) base = atomicAdd(&nmst, __popc(m));
                base = __shfl_sync(FULLM, base, ldr);
            }
            if (commit) {
                parent[t] = r;
                unsigned wm = (unsigned)(e >> 20);
                scratch[base + __popc(m & ltm)] =
                    ((unsigned long long)(~wm) << 32) | (e & 0xFFFFFull);
            }
        }
        __syncthreads();
        if (nmst == P) break;                // MST complete: exactly P unions
        if (t < NND) {
            parent[t] = parent[parent[t]];
            parent[t] = parent[parent[t]];   // unsynced 2nd jump: monotone-safe
            best[t] = 0ull;
        }
        __syncthreads();
        // deposit on shallow roots; relabel edge in place
        if (t < EC) {
            unsigned long long e = key[t];
            if (e != EMPTY64) {
                unsigned pr = (unsigned)(e & 0xFFFFFull);
                int a = (int)(pr >> 10), b = (int)(pr & 1023u);
                int q = parent[a]; while (parent[q] != q) q = parent[q];
                int pa = q;
                q = parent[b]; while (parent[q] != q) q = parent[q];
                int pb = q;
                if (pa != pb) {
                    unsigned long long off = (e & ~0xFFFFFull) |
                                             ((unsigned)pa << 10) | (unsigned)pb;
                    key[t] = off;
                    atomicMax(&best[pa], off);
                    atomicMax(&best[pb], off);
                } else {
                    key[t] = EMPTY64;      // internal: never useful again
                }
            }
        }
        __syncthreads();
    }

    // ---- Phase 6: sort MST edges ascending (== weight descending) ----
    if (t == 0) {
        int M = 256;
        while (M < nmst) M <<= 1;
        smem_M = M;
    }
    __syncthreads();
    const int M = smem_M;
    const int nm = nmst;
    if (t < M) key[t] = (t < nm) ? scratch[t] : EMPTY64;
    if (t < PMAX) node2[t] = make_int2(t, __float_as_int(cmaxv[t]));  // scan UF init
    __syncthreads();
    {
        const bool act = (warp << 6) < M;
        const int i0 = (warp << 6) + lane;
        const int i1 = i0 + 32;
        unsigned long long v0 = 0, v1 = 0;
        if (act) {
            v0 = key[i0]; v1 = key[i1];
            #pragma unroll
            for (int k2 = 2; k2 <= 64; k2 <<= 1) {
                if (k2 == 64) {
                    bool up = ((i0 & k2) == 0);
                    if ((v0 > v1) == up) { unsigned long long tm = v0; v0 = v1; v1 = tm; }
                }
                #pragma unroll
                for (int j = (k2 >= 32 ? 16 : (k2 >> 1)); j >= 1; j >>= 1) {
                    unsigned long long q0 = __shfl_xor_sync(FULLM, v0, j);
                    unsigned long long q1 = __shfl_xor_sync(FULLM, v1, j);
                    bool lower = (lane & j) == 0;
                    bool km0 = (lower == ((i0 & k2) == 0));
                    bool km1 = (lower == ((i1 & k2) == 0));
                    v0 = km0 ? (v0 < q0 ? v0 : q0) : (v0 > q0 ? v0 : q0);
                    v1 = km1 ? (v1 < q1 ? v1 : q1) : (v1 > q1 ? v1 : q1);
                }
            }
            key[i0] = v0; key[i1] = v1;
        }
        __syncthreads();
        for (int k2 = 128; k2 <= M; k2 <<= 1) {
            for (int j = k2 >> 1; j >= 64; j >>= 1) {
                if (t < (M >> 1)) {
                    int l = ((t & ~(j - 1)) << 1) | (t & (j - 1));
                    int m = l | j;
                    unsigned long long kl = key[l], km = key[m];
                    bool asc = ((l & k2) == 0);
                    if ((kl > km) == asc) { key[l] = km; key[m] = kl; }
                }
                __syncthreads();
            }
            if (act) {
                v0 = key[i0]; v1 = key[i1];
                {
                    bool up = ((i0 & k2) == 0);
                    if ((v0 > v1) == up) { unsigned long long tm = v0; v0 = v1; v1 = tm; }
                }
                #pragma unroll
                for (int j = 16; j >= 1; j >>= 1) {
                    unsigned long long q0 = __shfl_xor_sync(FULLM, v0, j);
                    unsigned long long q1 = __shfl_xor_sync(FULLM, v1, j);
                    bool lower = (lane & j) == 0;
                    bool km0 = (lower == ((i0 & k2) == 0));
                    bool km1 = (lower == ((i1 & k2) == 0));
                    v0 = km0 ? (v0 < q0 ? v0 : q0) : (v0 > q0 ? v0 : q0);
                    v1 = km1 ? (v1 < q1 ? v1 : q1) : (v1 > q1 ? v1 : q1);
                }
                key[i0] = v0; key[i1] = v1;
            }
            __syncthreads();
        }
    }

    // ---- Phase 7: warp-speculative elder-rule scan over sorted MST edges ----
    // 32 lanes pre-chase roots in parallel; lockstep sequential commit with
    // re-validation. Tree-edge subsets are acyclic, so every commit merges
    // distinct components; pair multiset identical to the serial scan.
    float* pwv = (float*)scratch;            // mst list dead after sort copy
    float* pdv = ((float*)scratch) + PMAX;
    if (warp == 0) {
        int np = 0;
        for (int base = 0; base < M; base += 32) {
            unsigned long long kk = key[base + lane];
            bool live = ((unsigned)(kk >> 32) != 0xFFFFFFFFu);
            unsigned livem = __ballot_sync(FULLM, live);
            if (livem == 0) break;
            int a0 = 0, b0 = 0, a = 0, b = 0;
            if (live) {
                a0 = (int)((kk >> 10) & 1023ull);
                b0 = (int)(kk & 1023ull);
                // speculative parallel pre-chase (read-only)
                a = a0; b = b0;
                int2 ra = node2[a];
                while (ra.x != a) { a = ra.x; ra = node2[a]; }
                int2 rb = node2[b];
                while (rb.x != b) { b = rb.x; rb = node2[b]; }
            }
            const int kmax = 32 - __clz(livem) ? 32 : 32;  // livem contiguous from 0
            #pragma unroll 1
            for (int k = 0; k < 32; k++) {
                if (!((livem >> k) & 1u)) break;   // sorted: live lanes contiguous
                int em = 0;
                if (lane == k) {
                    // finish chase on current state (stores by earlier lanes visible)
                    int2 ra = node2[a];
                    while (ra.x != a) { a = ra.x; ra = node2[a]; }
                    int2 rb = node2[b];
                    while (rb.x != b) { b = rb.x; rb = node2[b]; }
                    float w = invmonof(~(unsigned)(kk >> 32));
                    float Ma = __int_as_float(ra.y), Mb = __int_as_float(rb.y);
                    float die = fminf(Ma, Mb);
                    if (die > w) { pwv[np] = w; pdv[np] = die; em = 1; }
                    int win, lose;
                    if (Ma >= Mb) { win = a; lose = b; }
                    else          { win = b; lose = a; }
                    node2[lose].x = win;
                    node2[a0].x = win;
                    node2[b0].x = win;
                }
                __syncwarp(FULLM);                 // order stores before next commit
                np += __shfl_sync(FULLM, em, k);
            }
            if (livem != FULLM) break;
        }
        if (lane == 0) npairs = np;
    }
    __syncthreads();

    // ---- Phase 8: rank pairs by persistence desc, emit top CARD, pad ----
    const int np = npairs;
    if (t < np) {
        float pi = pdv[t] - pwv[t];
        int rank = 0;
        for (int j = 0; j < np; j++) {
            float pj = pdv[j] - pwv[j];
            rank += (pj > pi) || (pj == pi && j > t);
        }
        if (rank < CARD) {
            out[2 * rank]     = pwv[t];
            out[2 * rank + 1] = pdv[t];
        }
    }
    if (t < CARD && t >= np) {
        float pad = Ip[0];
        out[2 * t]     = pad;
        out[2 * t + 1] = pad;
    }
}

extern "C" void kernel_launch(void* const* d_in, const int* in_sizes, int n_in,
                              void* d_out, int out_size) {
    const float* I = (const float*)d_in[0];   // (28,28,2) float32
    const float* p = (const float*)d_in[1];   // (2,1) float32
    float* out = (float*)d_out;               // 100 float32
    (void)in_sizes; (void)n_in; (void)out_size;
    cubical_kernel<<<1, NT>>>(I, p, out);
}

// round 16
// speedup vs baseline: 1.1816x; 1.1816x over previous
#include <cuda_runtime.h>

#define H 28
#define W 28
#define NSQ (H * W)          // 784 pixels
#define NE_H (H * (W - 1))   // 756
#define NE_V ((H - 1) * W)   // 756
#define NE_B (2 * H + 2 * W) // 112
#define NE (NE_H + NE_V + NE_B) // 1624
#define NT 1024
#define KMAX 1024
#define HSZ 1024
#define PMAX 512             // max dense nodes (peaks + outer); true max 393
#define CARD 50
#define EMPTY64 0xFFFFFFFFFFFFFFFFull

__device__ __forceinline__ unsigned monof(float x) {
    unsigned u = __float_as_uint(x);
    return (u & 0x80000000u) ? ~u : (u | 0x80000000u);
}
__device__ __forceinline__ float invmonof(unsigned m) {
    return __uint_as_float((m & 0x80000000u) ? (m ^ 0x80000000u) : ~m);
}

__global__ __launch_bounds__(NT, 1)
void cubical_kernel(const float* __restrict__ I, const float* __restrict__ p,
                    float* __restrict__ out) {
    __shared__ float Ip[NSQ];
    __shared__ short g[NSQ];                    // ascent ptr -> peak -> dense id
    __shared__ short lbl[NSQ];                  // peak pixel -> dense id
    __shared__ unsigned long long key[KMAX];    // deduped edges / sort buffer
    __shared__ unsigned long long scratch[HSZ]; // hash -> mst list -> pw/pd
    __shared__ int   parent[PMAX];              // Boruvka UF
    __shared__ float cmaxv[PMAX];
    __shared__ unsigned long long best[PMAX];
    __shared__ int2  node2[PMAX];               // scan UF: .x parent, .y cmax bits
    __shared__ int cnt_peaks, ecnt, nmst, npairs, smem_M;

    const int t = threadIdx.x;
    const int lane = t & 31;
    const int warp = t >> 5;
    const float p0 = p[0], p1 = p[1];

    // ---- Phase 1: Ip = I.p, init ----
    if (t < NSQ) Ip[t] = fmaf(I[2 * t], p0, I[2 * t + 1] * p1);
    if (t == 0) { cnt_peaks = 0; ecnt = 0; nmst = 0; npairs = 0; }
    if (t < HSZ) scratch[t] = EMPTY64;
    if (t < PMAX) { parent[t] = t; best[t] = 0ull; }
    __syncthreads();

    // ---- Phase 2: steepest-ascent pointer ----
    if (t < NSQ) {
        const int row = t / W, col = t - row * W;
        float bf = Ip[t]; int bid = t;
        if (col > 0)     { float f = Ip[t - 1]; if (f > bf) { bf = f; bid = t - 1; } }
        if (col < W - 1) { float f = Ip[t + 1]; if (f > bf) { bf = f; bid = t + 1; } }
        if (row > 0)     { float f = Ip[t - W]; if (f > bf) { bf = f; bid = t - W; } }
        if (row < H - 1) { float f = Ip[t + W]; if (f > bf) { bf = f; bid = t + W; } }
        g[t] = (short)bid;
    }
    __syncthreads();

    // ---- Phase 3: register chase to peak (read-only ascent forest: acyclic) ----
    short gfin = 0;
    if (t < NSQ) {
        int x = t, gx = g[x];
        while (gx != x) { x = gx; gx = g[x]; }
        gfin = (short)x;
    }
    __syncthreads();
    if (t < NSQ) g[t] = gfin;
    __syncthreads();

    // ---- Phase 3.5: dense relabel of peaks ----
    if (t < NSQ && g[t] == (short)t) {
        int id = atomicAdd(&cnt_peaks, 1);
        lbl[t] = (short)id;
        cmaxv[id] = Ip[t];
    }
    __syncthreads();
    const int P = cnt_peaks;      // outer id = P
    const int NND = P + 1;
    if (t == 0) cmaxv[P] = 3.0e38f;
    short gdense = 0;
    if (t < NSQ) gdense = lbl[g[t]];
    __syncthreads();
    if (t < NSQ) g[t] = gdense;
    __syncthreads();

    // ---- Phase 4: hash dedup (max weight per peak pair) ----
    for (int i = t; i < NE; i += NT) {
        int pu, pv; float w;
        if (i < NE_H) {
            int r = i / (W - 1), c = i % (W - 1);
            int u = r * W + c, v = u + 1;
            w = fminf(Ip[u], Ip[v]);
            pu = g[u]; pv = g[v];
        } else if (i < NE_H + NE_V) {
            int j = i - NE_H;
            int u = j, v = j + W;
            w = fminf(Ip[u], Ip[v]);
            pu = g[u]; pv = g[v];
        } else {
            int j = i - NE_H - NE_V;
            int sq;
            if (j < W)              sq = j;
            else if (j < 2 * W)     sq = (H - 1) * W + (j - W);
            else if (j < 2 * W + H) sq = (j - 2 * W) * W;
            else                    sq = (j - 2 * W - H) * W + (W - 1);
            w = Ip[sq];
            pu = g[sq]; pv = P;
        }
        if (pu != pv) {
            int pmin = pu < pv ? pu : pv;
            int pmax = pu < pv ? pv : pu;
            unsigned pair = ((unsigned)pmin << 10) | (unsigned)pmax;
            unsigned long long desired = ((unsigned long long)monof(w) << 20) | pair;
            unsigned s = (pair * 2654435761u) & (HSZ - 1);
            for (;;) {
                unsigned long long cur = scratch[s];
                if (cur == EMPTY64) {
                    unsigned long long old = atomicCAS(&scratch[s], EMPTY64, desired);
                    if (old == EMPTY64) break;
                    cur = old;
                }
                if ((unsigned)(cur & 0xFFFFFu) == pair) {
                    atomicMax(&scratch[s], desired);
                    break;
                }
                s = (s + 1) & (HSZ - 1);
            }
        }
    }
    __syncthreads();

    // ---- Phase 4.5: compact hash -> key[] AND round-0 deposit (roots = ids) ----
    if (t < HSZ) {
        unsigned long long e = scratch[t];
        if (e != EMPTY64) {
            int idx = atomicAdd(&ecnt, 1);
            key[idx] = e;
            unsigned pr = (unsigned)(e & 0xFFFFFull);
            atomicMax(&best[pr >> 10], e);
            atomicMax(&best[pr & 1023u], e);
        }
    }
    __syncthreads();
    const int EC = ecnt;

    // ---- Phase 5: Boruvka max-spanning-tree; exact exit at nmst == P ----
    for (int round = 0; round < 16; round++) {
        // fused hook + commit (parent[t] written only by thread t)
        if (t < NND) {
            unsigned long long e = best[t];
            if (e != 0ull && parent[t] == t) {
                int pa = (int)((e >> 10) & 1023ull);
                int pb = (int)(e & 1023ull);
                int r = (pa == t) ? pb : pa;
                unsigned long long er = best[r];
                int ra = (int)((er >> 10) & 1023ull);
                int rb = (int)(er & 1023ull);
                int rother = (ra == r) ? rb : ra;
                bool mutual = (rother == t);
                if (!(mutual && t < r)) {
                    parent[t] = r;
                    int idx = atomicAdd(&nmst, 1);
                    unsigned wm = (unsigned)(e >> 20);
                    scratch[idx] = ((unsigned long long)(~wm) << 32) | (e & 0xFFFFFull);
                }
            }
        }
        __syncthreads();
        if (nmst == P) break;                // MST complete: exactly P unions
        if (t < NND) {
            parent[t] = parent[parent[t]];
            parent[t] = parent[parent[t]];   // unsynced 2nd jump: monotone-safe
            best[t] = 0ull;
        }
        __syncthreads();
        // deposit on shallow roots; relabel edge in place
        if (t < EC) {
            unsigned long long e = key[t];
            if (e != EMPTY64) {
                unsigned pr = (unsigned)(e & 0xFFFFFull);
                int a = (int)(pr >> 10), b = (int)(pr & 1023u);
                int q = parent[a]; while (parent[q] != q) q = parent[q];
                int pa = q;
                q = parent[b]; while (parent[q] != q) q = parent[q];
                int pb = q;
                if (pa != pb) {
                    unsigned long long off = (e & ~0xFFFFFull) |
                                             ((unsigned)pa << 10) | (unsigned)pb;
                    key[t] = off;
                    atomicMax(&best[pa], off);
                    atomicMax(&best[pb], off);
                } else {
                    key[t] = EMPTY64;      // internal: never useful again
                }
            }
        }
        __syncthreads();
    }

    // ---- Phase 6: sort MST edges ascending (== weight descending) ----
    if (t == 0) {
        int M = 256;
        while (M < nmst) M <<= 1;
        smem_M = M;
    }
    __syncthreads();
    const int M = smem_M;
    const int nm = nmst;
    if (t < M) key[t] = (t < nm) ? scratch[t] : EMPTY64;
    if (t < PMAX) node2[t] = make_int2(t, __float_as_int(cmaxv[t]));  // scan UF init
    __syncthreads();
    {
        const bool act = (warp << 6) < M;
        const int i0 = (warp << 6) + lane;
        const int i1 = i0 + 32;
        unsigned long long v0 = 0, v1 = 0;
        const unsigned FULL = 0xffffffffu;
        if (act) {
            v0 = key[i0]; v1 = key[i1];
            #pragma unroll
            for (int k2 = 2; k2 <= 64; k2 <<= 1) {
                if (k2 == 64) {
                    bool up = ((i0 & k2) == 0);
                    if ((v0 > v1) == up) { unsigned long long tm = v0; v0 = v1; v1 = tm; }
                }
                #pragma unroll
                for (int j = (k2 >= 32 ? 16 : (k2 >> 1)); j >= 1; j >>= 1) {
                    unsigned long long q0 = __shfl_xor_sync(FULL, v0, j);
                    unsigned long long q1 = __shfl_xor_sync(FULL, v1, j);
                    bool lower = (lane & j) == 0;
                    bool km0 = (lower == ((i0 & k2) == 0));
                    bool km1 = (lower == ((i1 & k2) == 0));
                    v0 = km0 ? (v0 < q0 ? v0 : q0) : (v0 > q0 ? v0 : q0);
                    v1 = km1 ? (v1 < q1 ? v1 : q1) : (v1 > q1 ? v1 : q1);
                }
            }
            key[i0] = v0; key[i1] = v1;
        }
        __syncthreads();
        for (int k2 = 128; k2 <= M; k2 <<= 1) {
            for (int j = k2 >> 1; j >= 64; j >>= 1) {
                if (t < (M >> 1)) {
                    int l = ((t & ~(j - 1)) << 1) | (t & (j - 1));
                    int m = l | j;
                    unsigned long long kl = key[l], km = key[m];
                    bool asc = ((l & k2) == 0);
                    if ((kl > km) == asc) { key[l] = km; key[m] = kl; }
                }
                __syncthreads();
            }
            if (act) {
                v0 = key[i0]; v1 = key[i1];
                {
                    bool up = ((i0 & k2) == 0);
                    if ((v0 > v1) == up) { unsigned long long tm = v0; v0 = v1; v1 = tm; }
                }
                #pragma unroll
                for (int j = 16; j >= 1; j >>= 1) {
                    unsigned long long q0 = __shfl_xor_sync(FULL, v0, j);
                    unsigned long long q1 = __shfl_xor_sync(FULL, v1, j);
                    bool lower = (lane & j) == 0;
                    bool km0 = (lower == ((i0 & k2) == 0));
                    bool km1 = (lower == ((i1 & k2) == 0));
                    v0 = km0 ? (v0 < q0 ? v0 : q0) : (v0 > q0 ? v0 : q0);
                    v1 = km1 ? (v1 < q1 ? v1 : q1) : (v1 > q1 ? v1 : q1);
                }
                key[i0] = v0; key[i1] = v1;
            }
            __syncthreads();
        }
    }

    // ---- Phase 7: serial elder-rule scan (interleaved chases, prefetch) ----
    float* pwv = (float*)scratch;            // mst list dead after sort copy
    float* pdv = ((float*)scratch) + PMAX;
    if (t == 0) {
        int np = 0;
        unsigned long long kk = key[0];
        #pragma unroll 1
        for (int k = 0; k < M; k++) {
            unsigned long long kk_next = key[(k + 1) & (KMAX - 1)];  // prefetch (M<=512<KMAX: safe)
            unsigned wm = (unsigned)(kk >> 32);
            if (wm == 0xFFFFFFFFu) break;
            int a = (int)((kk >> 10) & 1023ull);
            int b = (int)(kk & 1023ull);
            const int a0 = a, b0 = b;
            int2 ra = node2[a];
            int2 rb = node2[b];
            bool da = (ra.x == a), db = (rb.x == b);
            while (!(da && db)) {
                if (!da) { a = ra.x; ra = node2[a]; da = (ra.x == a); }
                if (!db) { b = rb.x; rb = node2[b]; db = (rb.x == b); }
            }
            float w = invmonof(~wm);
            float Ma = __int_as_float(ra.y), Mb = __int_as_float(rb.y);
            float die = fminf(Ma, Mb);
            if (die > w) { pwv[np] = w; pdv[np] = die; np++; }
            int win, lose;
            if (Ma >= Mb) { win = a; lose = b; }
            else          { win = b; lose = a; }
            node2[lose].x = win;
            node2[a0].x = win;
            node2[b0].x = win;
            kk = kk_next;
        }
        npairs = np;
    }
    __syncthreads();

    // ---- Phase 8: rank pairs by persistence desc, emit top CARD, pad ----
    const int np = npairs;
    if (t < np) {
        float pi = pdv[t] - pwv[t];
        int rank = 0;
        for (int j = 0; j < np; j++) {
            float pj = pdv[j] - pwv[j];
            rank += (pj > pi) || (pj == pi && j > t);
        }
        if (rank < CARD) {
            out[2 * rank]     = pwv[t];
            out[2 * rank + 1] = pdv[t];
        }
    }
    if (t < CARD && t >= np) {
        float pad = Ip[0];
        out[2 * t]     = pad;
        out[2 * t + 1] = pad;
    }
}

extern "C" void kernel_launch(void* const* d_in, const int* in_sizes, int n_in,
                              void* d_out, int out_size) {
    const float* I = (const float*)d_in[0];   // (28,28,2) float32
    const float* p = (const float*)d_in[1];   // (2,1) float32
    float* out = (float*)d_out;               // 100 float32
    (void)in_sizes; (void)n_in; (void)out_size;
    cubical_kernel<<<1, NT>>>(I, p, out);
}